// round 6
// baseline (speedup 1.0000x reference)
#include <cuda_runtime.h>
#include <stdint.h>

#define NTHREADS 1024
#define NWARPS (NTHREADS / 32)
#define K1T 512
#define K1W (K1T / 32)
#define SPLIT 4
#define HBITS 13
#define NBINS (1 << HBITS)
#define BPT (NBINS / NTHREADS)      // bins per thread in K2/K3 = 8
#define CAP 2048                    // candidate buffer per row
#define NEED_S 330                  // suffix target in SAMPLES (1-of-4 subsample)
#define SAMPLING_EPS 1e-5f
#define MAXROWS 256
#define SHIFT 10.0f

// ---------------- global scratch ----------------
__device__ unsigned       g_maxmono[MAXROWS];
__device__ float          g_sum[MAXROWS];
__device__ unsigned       g_thr[MAXROWS];
__device__ float          g_rmax[MAXROWS];
__device__ float          g_lZ[MAXROWS];
__device__ unsigned short g_hist16[MAXROWS][SPLIT][NBINS];   // 16 MB partial hists

// order-preserving float -> uint32 map (and inverse)
__device__ __forceinline__ unsigned mono(float f) {
    unsigned u = __float_as_uint(f);
    return u ^ ((unsigned)(((int)u) >> 31) | 0x80000000u);
}
__device__ __forceinline__ float inv_mono(unsigned m) {
    unsigned u = (m & 0x80000000u) ? (m ^ 0x80000000u) : ~m;
    return __uint_as_float(u);
}

// one bitonic round's register-resident phases (j = jstart..1, jstart<=32).
// thread holds elements a at index i0 = 64*warp+lane, b at i1 = i0+32.
__device__ __forceinline__ void reg_round(unsigned long long& a, unsigned long long& b,
                                          int i0, int i1, int lane, int kk, int jstart) {
    const bool upa = ((i0 & kk) == 0);
    const bool upb = ((i1 & kk) == 0);
#pragma unroll
    for (int j = 32; j >= 1; j >>= 1) {
        if (j > jstart) continue;
        if (j == 32) {
            unsigned long long lo = a < b ? a : b;
            unsigned long long hi = a < b ? b : a;
            a = upa ? lo : hi;
            b = upa ? hi : lo;
        } else {
            const bool lower = ((lane & j) == 0);
            unsigned long long pa = __shfl_xor_sync(0xFFFFFFFFu, a, j);
            unsigned long long pb = __shfl_xor_sync(0xFFFFFFFFu, b, j);
            bool keepMinA = (lower == upa);
            bool keepMinB = (lower == upb);
            a = keepMinA ? (a < pa ? a : pa) : (a > pa ? a : pa);
            b = keepMinB ? (b < pb ? b : pb) : (b > pb ? b : pb);
        }
    }
}

// ======================================================================
// K0: zero per-row accumulators
// ======================================================================
__global__ void k0_init(int B) {
    int i = blockIdx.x * blockDim.x + threadIdx.x;
    if (i < B) { g_maxmono[i] = 0u; g_sum[i] = 0.f; }
}

// ======================================================================
// K1: grid = B*SPLIT. Each CTA streams V/SPLIT of one row:
//   branchless max + fixed-shift sum-exp + 1/4-subsampled smem histogram.
//   Ends: 1 atomicMax + 1 atomicAdd per CTA, plain u16 partial-hist store.
// ======================================================================
__global__ __launch_bounds__(K1T, 2) void k1_stream(const float* __restrict__ logits, int V) {
    const int bid = blockIdx.x;
    const int row = bid >> 2, sp = bid & 3;
    const int t = threadIdx.x;
    const int lane = t & 31, warp = t >> 5;

    __shared__ unsigned hist[NBINS];
    __shared__ float wm[K1W], ws[K1W];

    for (int z = t; z < NBINS; z += K1T) hist[z] = 0u;
    __syncthreads();

    const int chunk = V / SPLIT;
    const float* __restrict__ x = logits + (size_t)row * V + (size_t)sp * chunk;
    const int n4 = chunk >> 2;
    const float4* __restrict__ x4 = (const float4*)x;
    const float NEG_INF = __int_as_float(0xff800000);

    float m0 = NEG_INF, m1 = NEG_INF, m2 = NEG_INF, m3 = NEG_INF;
    float s0 = 0.f, s1 = 0.f, s2 = 0.f, s3 = 0.f;
    auto proc = [&](float4 v) {
        atomicAdd(&hist[mono(v.x) >> (32 - HBITS)], 1u);   // 1-of-4 subsample
        m0 = fmaxf(m0, v.x); m1 = fmaxf(m1, v.y);
        m2 = fmaxf(m2, v.z); m3 = fmaxf(m3, v.w);
        s0 += __expf(v.x - SHIFT); s1 += __expf(v.y - SHIFT);
        s2 += __expf(v.z - SHIFT); s3 += __expf(v.w - SHIFT);
    };
    int i = t;
    for (; i + 3 * K1T < n4; i += 4 * K1T) {
        float4 a = x4[i];
        float4 b = x4[i + K1T];
        float4 c = x4[i + 2 * K1T];
        float4 d = x4[i + 3 * K1T];
        proc(a); proc(b); proc(c); proc(d);
    }
    for (; i < n4; i += K1T) proc(x4[i]);

    float m = fmaxf(fmaxf(m0, m1), fmaxf(m2, m3));
    float s = (s0 + s1) + (s2 + s3);
#pragma unroll
    for (int off = 16; off; off >>= 1) {
        m = fmaxf(m, __shfl_xor_sync(0xFFFFFFFFu, m, off));
        s += __shfl_xor_sync(0xFFFFFFFFu, s, off);
    }
    if (lane == 0) { wm[warp] = m; ws[warp] = s; }
    __syncthreads();                       // hist + wm/ws complete
    if (t == 0) {
        float mm = wm[0], stot = ws[0];
#pragma unroll
        for (int w2 = 1; w2 < K1W; w2++) { mm = fmaxf(mm, wm[w2]); stot += ws[w2]; }
        atomicMax(&g_maxmono[row], mono(mm));
        atomicAdd(&g_sum[row], stot);
    }

    // store partial hist as u16 (coalesced uint4 stores; 16 consecutive bins/thread)
    {
        uint4* dst = (uint4*)g_hist16[row][sp];
        const int b0 = t * 16;
        unsigned p[8];
#pragma unroll
        for (int k2 = 0; k2 < 8; k2++) {
            unsigned lo = hist[b0 + 2 * k2]     & 0xFFFFu;
            unsigned hi = hist[b0 + 2 * k2 + 1] & 0xFFFFu;
            p[k2] = lo | (hi << 16);
        }
        dst[2 * t]     = make_uint4(p[0], p[1], p[2], p[3]);
        dst[2 * t + 1] = make_uint4(p[4], p[5], p[6], p[7]);
    }
}

// ======================================================================
// K2: grid = B. Sum 4 partial hists, shuffle suffix-scan -> thr, rmax, logZ.
// ======================================================================
__global__ __launch_bounds__(NTHREADS) void k2_thresh(int B) {
    const int row = blockIdx.x;
    const int t = threadIdx.x;
    const int lane = t & 31, warp = t >> 5;

    __shared__ unsigned wu[NWARPS];
    __shared__ unsigned s_bin;
    if (t == 0) s_bin = 0u;

    // my 8 consecutive bins summed over 4 splits (each uint4 = 8 u16)
    unsigned cnt[BPT];
#pragma unroll
    for (int b = 0; b < BPT; b++) cnt[b] = 0u;
#pragma unroll
    for (int sp = 0; sp < SPLIT; sp++) {
        uint4 h = ((const uint4*)g_hist16[row][sp])[t];
        cnt[0] += h.x & 0xFFFFu; cnt[1] += h.x >> 16;
        cnt[2] += h.y & 0xFFFFu; cnt[3] += h.y >> 16;
        cnt[4] += h.z & 0xFFFFu; cnt[5] += h.z >> 16;
        cnt[6] += h.w & 0xFFFFu; cnt[7] += h.w >> 16;
    }
    unsigned csum = 0;
#pragma unroll
    for (int b = 0; b < BPT; b++) csum += cnt[b];

    unsigned iv = csum;
#pragma unroll
    for (int off = 1; off < 32; off <<= 1) {
        unsigned nb = __shfl_up_sync(0xFFFFFFFFu, iv, off);
        if (lane >= off) iv += nb;
    }
    if (lane == 31) wu[warp] = iv;
    __syncthreads();
    if (warp == 0) {
        unsigned wv = wu[lane];
#pragma unroll
        for (int off = 1; off < 32; off <<= 1) {
            unsigned nb = __shfl_up_sync(0xFFFFFFFFu, wv, off);
            if (lane >= off) wv += nb;
        }
        wu[lane] = wv;
    }
    __syncthreads();
    unsigned incl = iv + (warp ? wu[warp - 1] : 0u);
    unsigned Total = wu[NWARPS - 1];
    unsigned above = Total - incl;
    unsigned acc = above, prev = above;
#pragma unroll
    for (int b = BPT - 1; b >= 0; b--) {
        acc += cnt[b];                    // = suffix(bin t*BPT+b) in samples
        if (acc >= NEED_S && prev < NEED_S) s_bin = (unsigned)(t * BPT + b);
        prev = acc;
    }
    __syncthreads();
    if (t == 0) {
        g_thr[row] = s_bin << (32 - HBITS);
        g_rmax[row] = inv_mono(g_maxmono[row]);
        g_lZ[row] = SHIFT + logf(g_sum[row]);
    }
}

// ======================================================================
// K3: grid = B. Collect candidates (L2-hot), hybrid bitonic sort,
//     min-p/top-k/top-p, race sampling, top-20 logprobs, rank, outputs.
// ======================================================================
__global__ __launch_bounds__(NTHREADS, 1) void k3_sample(
    const float* __restrict__ logits,
    const float* __restrict__ temperature,
    const float* __restrict__ min_p,
    const int*   __restrict__ top_k,
    const float* __restrict__ top_p,
    const float* __restrict__ q,
    float* __restrict__ out,
    int B, int V, int C)
{
    const int row = blockIdx.x;
    const int t = threadIdx.x;
    const int lane = t & 31, warp = t >> 5;

    __shared__ __align__(16) unsigned char sbuf[CAP * 8 + CAP * 4 + CAP * 4];
    __shared__ float wf[NWARPS];
    __shared__ int wi[NWARPS], wr[NWARPS];
    __shared__ int s_cnt, s_m, s_S, s_rank, s_sampled, s_rstar;

    unsigned long long* key = (unsigned long long*)sbuf;
    float* e  = (float*)(sbuf + CAP * 8);
    float* hd = (float*)(sbuf + CAP * 8 + CAP * 4);

    if (t == 0) { s_cnt = 0; s_m = 0; s_S = 0; s_rank = 0; }
    __syncthreads();

    const unsigned thr = g_thr[row];
    const float rmax = g_rmax[row];
    const float lZ   = g_lZ[row];

    const float* __restrict__ x = logits + (size_t)row * V;
    const int V4 = V >> 2;
    const float4* __restrict__ x4 = (const float4*)x;

    auto procB = [&](float4 v, int base) {
        unsigned u;
        u = mono(v.x); if (u >= thr) { int p = atomicAdd(&s_cnt, 1); if (p < CAP) key[p] = ((unsigned long long)u << 32) | (unsigned)~(unsigned)(base + 0); }
        u = mono(v.y); if (u >= thr) { int p = atomicAdd(&s_cnt, 1); if (p < CAP) key[p] = ((unsigned long long)u << 32) | (unsigned)~(unsigned)(base + 1); }
        u = mono(v.z); if (u >= thr) { int p = atomicAdd(&s_cnt, 1); if (p < CAP) key[p] = ((unsigned long long)u << 32) | (unsigned)~(unsigned)(base + 2); }
        u = mono(v.w); if (u >= thr) { int p = atomicAdd(&s_cnt, 1); if (p < CAP) key[p] = ((unsigned long long)u << 32) | (unsigned)~(unsigned)(base + 3); }
    };
    int i = t;
    for (; i + 3 * NTHREADS < V4; i += 4 * NTHREADS) {
        float4 a = x4[i];
        float4 b = x4[i + NTHREADS];
        float4 c = x4[i + 2 * NTHREADS];
        float4 d = x4[i + 3 * NTHREADS];
        procB(a, 4 * i);
        procB(b, 4 * (i + NTHREADS));
        procB(c, 4 * (i + 2 * NTHREADS));
        procB(d, 4 * (i + 3 * NTHREADS));
    }
    for (; i < V4; i += NTHREADS) procB(x4[i], 4 * i);
    for (int j = (V4 << 2) + t; j < V; j += NTHREADS) {
        unsigned u = mono(x[j]);
        if (u >= thr) { int p = atomicAdd(&s_cnt, 1); if (p < CAP) key[p] = ((unsigned long long)u << 32) | (unsigned)~(unsigned)j; }
    }
    __syncthreads();
    const int n = min(s_cnt, CAP);
    for (int z = n + t; z < CAP; z += NTHREADS) key[z] = 0ULL;  // sentinel
    __syncthreads();

    // ---------------- hybrid bitonic sort (ascending) --------------------------
    const int i0 = 64 * warp + lane;
    const int i1 = i0 + 32;
    {
        unsigned long long a = key[i0], b = key[i1];
#pragma unroll
        for (int kk = 2; kk <= 64; kk <<= 1)
            reg_round(a, b, i0, i1, lane, kk, (kk >> 1) > 32 ? 32 : (kk >> 1));
        key[i0] = a; key[i1] = b;
        __syncthreads();
        for (int kk = 128; kk <= CAP; kk <<= 1) {
            for (int j = kk >> 1; j >= 64; j >>= 1) {
#pragma unroll
                for (int w2 = 0; w2 < CAP / NTHREADS; w2++) {
                    int idx = t + w2 * NTHREADS;
                    int l2 = idx ^ j;
                    if (l2 > idx) {
                        unsigned long long av = key[idx], bv = key[l2];
                        bool sw = ((idx & kk) == 0) ? (av > bv) : (av < bv);
                        if (sw) { key[idx] = bv; key[l2] = av; }
                    }
                }
                __syncthreads();
            }
            a = key[i0]; b = key[i1];
            reg_round(a, b, i0, i1, lane, kk, 32);
            key[i0] = a; key[i1] = b;
            __syncthreads();
        }
    }

#define DKEY(r) (key[CAP - 1 - (r)])
#define DVAL(r) inv_mono((unsigned)(DKEY(r) >> 32))
#define DIDX(r) ((int)(~(unsigned)DKEY(r)))

    // ---------------- per-row scalars ----------------
    const float temp = temperature[row];
    const float mp   = min_p[row];
    const float tp   = top_p[row];
    int kk_ = top_k[row];
    kk_ = max(1, min(kk_, V));
    const float t_mp = rmax + temp * logf(mp);

    for (int r = t; r < n; r += NTHREADS)
        if (DVAL(r) >= t_mp) atomicAdd(&s_m, 1);
    __syncthreads();
    const int mcnt = s_m;

    if (mcnt >= kk_) {
        float kth = DVAL(kk_ - 1);
        for (int r = t; r < n; r += NTHREADS)
            if (DVAL(r) >= kth) atomicAdd(&s_S, 1);
    }
    __syncthreads();
    const int S = (mcnt >= kk_) ? min(s_S, CAP) : mcnt;

    const bool greedy = (temp < SAMPLING_EPS);
    int sampled, rstar;

    if (!greedy) {
        const float lt0 = DVAL(0) / temp;
        for (int r = t; r < CAP; r += NTHREADS) {
            float ev = 0.f;
            if (r < S) ev = expf(DVAL(r) / temp - lt0);
            e[r] = ev;
        }
        __syncthreads();

        float a0 = e[2 * t], a1 = e[2 * t + 1];
        float tsum = a0 + a1;
        float sv = tsum;
#pragma unroll
        for (int off = 1; off < 32; off <<= 1) {
            float nb = __shfl_up_sync(0xFFFFFFFFu, sv, off);
            if (lane >= off) sv += nb;
        }
        if (lane == 31) wf[warp] = sv;
        __syncthreads();
        if (warp == 0) {
            float wv = wf[lane];
#pragma unroll
            for (int off = 1; off < 32; off <<= 1) {
                float nb = __shfl_up_sync(0xFFFFFFFFu, wv, off);
                if (lane >= off) wv += nb;
            }
            wf[lane] = wv;
        }
        __syncthreads();
        float inclf = sv + (warp ? wf[warp - 1] : 0.f);
        const float Z = wf[NWARPS - 1];
        float excl = inclf - tsum;
        hd[2 * t]     = excl;
        hd[2 * t + 1] = excl + a0;
        __syncthreads();

        const float c1 = (1.f - tp) * Z;
        const float* __restrict__ qrow = q + (size_t)row * V;
        float best = -1.f;
        int bidx = 0x7FFFFFFF, brr = 0;
        for (int r = t; r < S; r += NTHREADS) {
            if (r == 0 || (Z - hd[r]) > c1) {
                int id = DIDX(r);
                float qv = qrow[id];
                float ex = -logf(fmaxf(qv, 1e-10f));
                float sc = e[r] / ex;
                if (sc > best || (sc == best && id < bidx)) { best = sc; bidx = id; brr = r; }
            }
        }
#pragma unroll
        for (int off = 16; off; off >>= 1) {
            float ob = __shfl_down_sync(0xFFFFFFFFu, best, off);
            int   oi = __shfl_down_sync(0xFFFFFFFFu, bidx, off);
            int   orr = __shfl_down_sync(0xFFFFFFFFu, brr, off);
            if (ob > best || (ob == best && oi < bidx)) { best = ob; bidx = oi; brr = orr; }
        }
        if (lane == 0) { wf[warp] = best; wi[warp] = bidx; wr[warp] = brr; }
        __syncthreads();
        if (warp == 0) {
            best = wf[lane]; bidx = wi[lane]; brr = wr[lane];
#pragma unroll
            for (int off = 16; off; off >>= 1) {
                float ob = __shfl_down_sync(0xFFFFFFFFu, best, off);
                int   oi = __shfl_down_sync(0xFFFFFFFFu, bidx, off);
                int   orr = __shfl_down_sync(0xFFFFFFFFu, brr, off);
                if (ob > best || (ob == best && oi < bidx)) { best = ob; bidx = oi; brr = orr; }
            }
            if (lane == 0) { s_sampled = bidx; s_rstar = brr; }
        }
        __syncthreads();
        sampled = s_sampled;
        rstar = s_rstar;
    } else {
        sampled = DIDX(0);
        rstar = 0;
    }

    const float vstar = DVAL(rstar);
    const float tlp = vstar - lZ;
    for (int r = t; r < n; r += NTHREADS) {
        if ((DVAL(r) - lZ) >= tlp) atomicAdd(&s_rank, 1);
    }
    __syncthreads();

    if (t == 0) {
        out[row] = (float)sampled;
        out[(size_t)B + (size_t)row * C] = (float)sampled;
        out[(size_t)B + (size_t)B * C + (size_t)row * C] = tlp;
        out[(size_t)B + 2 * (size_t)B * C + row] = (float)s_rank;
    }
    if (t >= 1 && t < C) {
        int r = t - 1;
        unsigned long long kv = DKEY(r);
        out[(size_t)B + (size_t)row * C + t] = (float)(~(unsigned)kv);
        out[(size_t)B + (size_t)B * C + (size_t)row * C + t] = inv_mono((unsigned)(kv >> 32)) - lZ;
    }
#undef DKEY
#undef DVAL
#undef DIDX
}

// ======================================================================
extern "C" void kernel_launch(void* const* d_in, const int* in_sizes, int n_in,
                              void* d_out, int out_size) {
    const float* logits      = (const float*)d_in[0];
    const float* temperature = (const float*)d_in[1];
    const float* min_p       = (const float*)d_in[2];
    const int*   top_k       = (const int*)d_in[3];
    const float* top_p       = (const float*)d_in[4];
    const float* q           = (const float*)d_in[5];

    int B = in_sizes[1];
    int V = in_sizes[0] / B;
    int C = (out_size / B - 2) / 2;   // num_logprobs + 1

    k0_init<<<(B + 255) / 256, 256>>>(B);
    k1_stream<<<B * SPLIT, K1T>>>(logits, V);
    k2_thresh<<<B, NTHREADS>>>(B);
    k3_sample<<<B, NTHREADS>>>(logits, temperature, min_p, top_k, top_p, q,
                               (float*)d_out, B, V, C);
}

// round 7
// speedup vs baseline: 1.0065x; 1.0065x over previous
#include <cuda_runtime.h>
#include <stdint.h>

#define NTHREADS 1024
#define NWARPS (NTHREADS / 32)
#define HBITS 13
#define NBINS (1 << HBITS)
#define BPT (NBINS / NTHREADS)      // bins per thread = 8
#define CAP 2048                    // candidate buffer per row
#define SAMP 16384                  // sample size for threshold estimation
#define SAMPLING_EPS 1e-5f

// order-preserving float -> uint32 map (and inverse)
__device__ __forceinline__ unsigned mono(float f) {
    unsigned u = __float_as_uint(f);
    return u ^ ((unsigned)(((int)u) >> 31) | 0x80000000u);
}
__device__ __forceinline__ float inv_mono(unsigned m) {
    unsigned u = (m & 0x80000000u) ? (m ^ 0x80000000u) : ~m;
    return __uint_as_float(u);
}

// one bitonic round's register-resident phases (j = jstart..1, jstart<=32).
// thread holds elements a at index i0 = 64*warp+lane, b at i1 = i0+32.
__device__ __forceinline__ void reg_round(unsigned long long& a, unsigned long long& b,
                                          int i0, int i1, int lane, int kk, int jstart) {
    const bool upa = ((i0 & kk) == 0);
    const bool upb = ((i1 & kk) == 0);
#pragma unroll
    for (int j = 32; j >= 1; j >>= 1) {
        if (j > jstart) continue;
        if (j == 32) {
            unsigned long long lo = a < b ? a : b;
            unsigned long long hi = a < b ? b : a;
            a = upa ? lo : hi;
            b = upa ? hi : lo;
        } else {
            const bool lower = ((lane & j) == 0);
            unsigned long long pa = __shfl_xor_sync(0xFFFFFFFFu, a, j);
            unsigned long long pb = __shfl_xor_sync(0xFFFFFFFFu, b, j);
            bool keepMinA = (lower == upa);
            bool keepMinB = (lower == upb);
            a = keepMinA ? (a < pa ? a : pa) : (a > pa ? a : pa);
            b = keepMinB ? (b < pb ? b : pb) : (b > pb ? b : pb);
        }
    }
}

// block-wide: suffix-scan 13-bit histogram, return threshold key for
// "largest bin whose suffix count >= need". All threads must call.
__device__ unsigned find_thr(unsigned* hist, unsigned need, unsigned* wu, unsigned* s_bin) {
    const int t = threadIdx.x, lane = t & 31, warp = t >> 5;
    if (t == 0) *s_bin = 0u;
    __syncthreads();                 // hist atomics complete + s_bin init
    unsigned cnt[BPT];
    unsigned csum = 0;
#pragma unroll
    for (int b = 0; b < BPT; b++) { cnt[b] = hist[t * BPT + b]; csum += cnt[b]; }
    unsigned iv = csum;
#pragma unroll
    for (int off = 1; off < 32; off <<= 1) {
        unsigned nb = __shfl_up_sync(0xFFFFFFFFu, iv, off);
        if (lane >= off) iv += nb;
    }
    if (lane == 31) wu[warp] = iv;
    __syncthreads();
    if (warp == 0) {
        unsigned wv = wu[lane];
#pragma unroll
        for (int off = 1; off < 32; off <<= 1) {
            unsigned nb = __shfl_up_sync(0xFFFFFFFFu, wv, off);
            if (lane >= off) wv += nb;
        }
        wu[lane] = wv;
    }
    __syncthreads();
    unsigned incl = iv + (warp ? wu[warp - 1] : 0u);
    unsigned Total = wu[NWARPS - 1];
    unsigned above = Total - incl;
    unsigned acc = above, prev = above;
#pragma unroll
    for (int b = BPT - 1; b >= 0; b--) {
        acc += cnt[b];               // = suffix(bin t*BPT+b)
        if (acc >= need && prev < need) *s_bin = (unsigned)(t * BPT + b);
        prev = acc;
    }
    __syncthreads();
    return (*s_bin) << (32 - HBITS);
}

// ======================================================================
// Fused sampler, ONE full-row read:
//   sample 16K elems -> histogram -> threshold estimate
//   single full pass: max + sum-exp + candidate collection
//   (exact-histogram fallback if the sampled threshold misses bounds)
//   hybrid bitonic sort, min-p/top-k/top-p, race sampling, top-20, rank
// ======================================================================
__global__ __launch_bounds__(NTHREADS, 1) void sampler_fused(
    const float* __restrict__ logits,
    const float* __restrict__ temperature,
    const float* __restrict__ min_p,
    const int*   __restrict__ top_k,
    const float* __restrict__ top_p,
    const float* __restrict__ q,
    float* __restrict__ out,
    int B, int V, int C)
{
    const int row = blockIdx.x;
    const int t = threadIdx.x;
    const int lane = t & 31, warp = t >> 5;

    // 32KB buffer: hist[8192 u32]  OR  key[2048 u64] | e[2048 f32] | hd[2048 f32]
    __shared__ __align__(16) unsigned char sbuf[NBINS * 4];
    __shared__ float wf[NWARPS], wsx[NWARPS];
    __shared__ unsigned wu[NWARPS];
    __shared__ int wi[NWARPS], wr[NWARPS];
    __shared__ unsigned s_bin;
    __shared__ int s_cnt, s_m, s_S, s_rank, s_sampled, s_rstar;
    __shared__ float s_stat[2];   // [0]=rmax [1]=logZ

    unsigned* hist = (unsigned*)sbuf;
    unsigned long long* key = (unsigned long long*)sbuf;
    float* e  = (float*)(sbuf + CAP * 8);
    float* hd = (float*)(sbuf + CAP * 8 + CAP * 4);

    if (t == 0) { s_cnt = 0; s_m = 0; s_S = 0; s_rank = 0; }
#pragma unroll
    for (int z = t; z < NBINS; z += NTHREADS) hist[z] = 0u;
    __syncthreads();

    const float* __restrict__ x = logits + (size_t)row * V;
    const int V4 = V >> 2;
    const float4* __restrict__ x4 = (const float4*)x;
    const float NEG_INF = __int_as_float(0xff800000);

    // ---------------- sample phase: first SAMP elements -> histogram ----------
    const int SQ = min(SAMP, V & ~3) >> 2;
    for (int i = t; i < SQ; i += NTHREADS) {
        float4 v = x4[i];
        atomicAdd(&hist[mono(v.x) >> (32 - HBITS)], 1u);
        atomicAdd(&hist[mono(v.y) >> (32 - HBITS)], 1u);
        atomicAdd(&hist[mono(v.z) >> (32 - HBITS)], 1u);
        atomicAdd(&hist[mono(v.w) >> (32 - HBITS)], 1u);
    }
    // target: E[true count] ~ 1500
    unsigned need_samp = (unsigned)max(1ll, (1500ll * (long long)(SQ * 4)) / (long long)V);
    unsigned thr = find_thr(hist, need_samp, wu, &s_bin);   // syncs inside

    // ---------------- single full pass: max + sum-exp + collect ---------------
    float m0 = NEG_INF, m1 = NEG_INF, m2 = NEG_INF, m3 = NEG_INF;
    float s0 = 0.f, s1 = 0.f, s2 = 0.f, s3 = 0.f;
    auto procF = [&](float4 v, int base) {
        m0 = fmaxf(m0, v.x); m1 = fmaxf(m1, v.y);
        m2 = fmaxf(m2, v.z); m3 = fmaxf(m3, v.w);
        s0 += __expf(v.x); s1 += __expf(v.y);
        s2 += __expf(v.z); s3 += __expf(v.w);
        unsigned u;
        u = mono(v.x); if (u >= thr) { int p = atomicAdd(&s_cnt, 1); if (p < CAP) key[p] = ((unsigned long long)u << 32) | (unsigned)~(unsigned)(base + 0); }
        u = mono(v.y); if (u >= thr) { int p = atomicAdd(&s_cnt, 1); if (p < CAP) key[p] = ((unsigned long long)u << 32) | (unsigned)~(unsigned)(base + 1); }
        u = mono(v.z); if (u >= thr) { int p = atomicAdd(&s_cnt, 1); if (p < CAP) key[p] = ((unsigned long long)u << 32) | (unsigned)~(unsigned)(base + 2); }
        u = mono(v.w); if (u >= thr) { int p = atomicAdd(&s_cnt, 1); if (p < CAP) key[p] = ((unsigned long long)u << 32) | (unsigned)~(unsigned)(base + 3); }
    };
    int i = t;
    for (; i + 3 * NTHREADS < V4; i += 4 * NTHREADS) {
        float4 a = x4[i];
        float4 b = x4[i + NTHREADS];
        float4 c = x4[i + 2 * NTHREADS];
        float4 d = x4[i + 3 * NTHREADS];
        procF(a, 4 * i);
        procF(b, 4 * (i + NTHREADS));
        procF(c, 4 * (i + 2 * NTHREADS));
        procF(d, 4 * (i + 3 * NTHREADS));
    }
    for (; i < V4; i += NTHREADS) procF(x4[i], 4 * i);
    for (int j = (V4 << 2) + t; j < V; j += NTHREADS) {
        float v = x[j];
        m0 = fmaxf(m0, v);
        s0 += __expf(v);
        unsigned u = mono(v);
        if (u >= thr) { int p = atomicAdd(&s_cnt, 1); if (p < CAP) key[p] = ((unsigned long long)u << 32) | (unsigned)~(unsigned)j; }
    }

    // block reduce max & sum
    float m = fmaxf(fmaxf(m0, m1), fmaxf(m2, m3));
    float s = (s0 + s1) + (s2 + s3);
#pragma unroll
    for (int off = 16; off; off >>= 1) {
        m = fmaxf(m, __shfl_xor_sync(0xFFFFFFFFu, m, off));
        s += __shfl_xor_sync(0xFFFFFFFFu, s, off);
    }
    if (lane == 0) { wf[warp] = m; wsx[warp] = s; }
    __syncthreads();                 // key writes + s_cnt final + wf/wsx visible
    if (t == 0) {
        float mm = wf[0], stot = wsx[0];
#pragma unroll
        for (int w2 = 1; w2 < NWARPS; w2++) { mm = fmaxf(mm, wf[w2]); stot += wsx[w2]; }
        s_stat[0] = mm;
        s_stat[1] = logf(stot);
    }
    __syncthreads();

    // ---------------- check + exact fallback (rare; uniform branch) -----------
    int kclip = top_k[row];
    kclip = max(1, min(kclip, V));
    const int needed = min(max(kclip, 32), CAP);
    if (s_cnt < needed || s_cnt > CAP) {
        // exact full histogram (clobbers keys), then recollect
#pragma unroll
        for (int z = t; z < NBINS; z += NTHREADS) hist[z] = 0u;
        __syncthreads();
        for (int ii = t; ii < V4; ii += NTHREADS) {
            float4 v = x4[ii];
            atomicAdd(&hist[mono(v.x) >> (32 - HBITS)], 1u);
            atomicAdd(&hist[mono(v.y) >> (32 - HBITS)], 1u);
            atomicAdd(&hist[mono(v.z) >> (32 - HBITS)], 1u);
            atomicAdd(&hist[mono(v.w) >> (32 - HBITS)], 1u);
        }
        for (int j = (V4 << 2) + t; j < V; j += NTHREADS)
            atomicAdd(&hist[mono(x[j]) >> (32 - HBITS)], 1u);
        thr = find_thr(hist, (unsigned)needed, wu, &s_bin);   // syncs inside
        if (t == 0) s_cnt = 0;
        __syncthreads();
        for (int ii = t; ii < V4; ii += NTHREADS) {
            float4 v = x4[ii];
            unsigned u;
            u = mono(v.x); if (u >= thr) { int p = atomicAdd(&s_cnt, 1); if (p < CAP) key[p] = ((unsigned long long)u << 32) | (unsigned)~(unsigned)(4 * ii + 0); }
            u = mono(v.y); if (u >= thr) { int p = atomicAdd(&s_cnt, 1); if (p < CAP) key[p] = ((unsigned long long)u << 32) | (unsigned)~(unsigned)(4 * ii + 1); }
            u = mono(v.z); if (u >= thr) { int p = atomicAdd(&s_cnt, 1); if (p < CAP) key[p] = ((unsigned long long)u << 32) | (unsigned)~(unsigned)(4 * ii + 2); }
            u = mono(v.w); if (u >= thr) { int p = atomicAdd(&s_cnt, 1); if (p < CAP) key[p] = ((unsigned long long)u << 32) | (unsigned)~(unsigned)(4 * ii + 3); }
        }
        for (int j = (V4 << 2) + t; j < V; j += NTHREADS) {
            unsigned u = mono(x[j]);
            if (u >= thr) { int p = atomicAdd(&s_cnt, 1); if (p < CAP) key[p] = ((unsigned long long)u << 32) | (unsigned)~(unsigned)j; }
        }
        __syncthreads();
    }
    const int n = min(s_cnt, CAP);
    for (int z = n + t; z < CAP; z += NTHREADS) key[z] = 0ULL;  // sentinel
    __syncthreads();
    const float rmax = s_stat[0];
    const float lZ   = s_stat[1];

    // ---------------- hybrid bitonic sort (ascending) -------------------------
    const int i0 = 64 * warp + lane;
    const int i1 = i0 + 32;
    {
        unsigned long long a = key[i0], b = key[i1];
#pragma unroll
        for (int kk = 2; kk <= 64; kk <<= 1)
            reg_round(a, b, i0, i1, lane, kk, (kk >> 1) > 32 ? 32 : (kk >> 1));
        key[i0] = a; key[i1] = b;
        __syncthreads();
        for (int kk = 128; kk <= CAP; kk <<= 1) {
            for (int j = kk >> 1; j >= 64; j >>= 1) {
#pragma unroll
                for (int w2 = 0; w2 < CAP / NTHREADS; w2++) {
                    int idx = t + w2 * NTHREADS;
                    int l2 = idx ^ j;
                    if (l2 > idx) {
                        unsigned long long av = key[idx], bv = key[l2];
                        bool sw = ((idx & kk) == 0) ? (av > bv) : (av < bv);
                        if (sw) { key[idx] = bv; key[l2] = av; }
                    }
                }
                __syncthreads();
            }
            a = key[i0]; b = key[i1];
            reg_round(a, b, i0, i1, lane, kk, 32);
            key[i0] = a; key[i1] = b;
            __syncthreads();
        }
    }

#define DKEY(r) (key[CAP - 1 - (r)])
#define DVAL(r) inv_mono((unsigned)(DKEY(r) >> 32))
#define DIDX(r) ((int)(~(unsigned)DKEY(r)))

    // ---------------- per-row scalars ----------------
    const float temp = temperature[row];
    const float mp   = min_p[row];
    const float tp   = top_p[row];
    const int kk_ = kclip;
    const float t_mp = rmax + temp * logf(mp);

    for (int r = t; r < n; r += NTHREADS)
        if (DVAL(r) >= t_mp) atomicAdd(&s_m, 1);
    __syncthreads();
    const int mcnt = s_m;

    if (mcnt >= kk_) {
        float kth = DVAL(kk_ - 1);
        for (int r = t; r < n; r += NTHREADS)
            if (DVAL(r) >= kth) atomicAdd(&s_S, 1);
    }
    __syncthreads();
    const int S = (mcnt >= kk_) ? min(s_S, CAP) : mcnt;

    const bool greedy = (temp < SAMPLING_EPS);
    int sampled, rstar;

    if (!greedy) {
        const float lt0 = DVAL(0) / temp;
        for (int r = t; r < CAP; r += NTHREADS) {
            float ev = 0.f;
            if (r < S) ev = expf(DVAL(r) / temp - lt0);
            e[r] = ev;
        }
        __syncthreads();

        float a0 = e[2 * t], a1 = e[2 * t + 1];
        float tsum = a0 + a1;
        float sv = tsum;
#pragma unroll
        for (int off = 1; off < 32; off <<= 1) {
            float nb = __shfl_up_sync(0xFFFFFFFFu, sv, off);
            if (lane >= off) sv += nb;
        }
        if (lane == 31) wf[warp] = sv;
        __syncthreads();
        if (warp == 0) {
            float wv = wf[lane];
#pragma unroll
            for (int off = 1; off < 32; off <<= 1) {
                float nb = __shfl_up_sync(0xFFFFFFFFu, wv, off);
                if (lane >= off) wv += nb;
            }
            wf[lane] = wv;
        }
        __syncthreads();
        float inclf = sv + (warp ? wf[warp - 1] : 0.f);
        const float Z = wf[NWARPS - 1];
        float excl = inclf - tsum;
        hd[2 * t]     = excl;
        hd[2 * t + 1] = excl + a0;
        __syncthreads();

        const float c1 = (1.f - tp) * Z;
        const float* __restrict__ qrow = q + (size_t)row * V;
        float best = -1.f;
        int bidx = 0x7FFFFFFF, brr = 0;
        for (int r = t; r < S; r += NTHREADS) {
            if (r == 0 || (Z - hd[r]) > c1) {
                int id = DIDX(r);
                float qv = qrow[id];
                float ex = -logf(fmaxf(qv, 1e-10f));
                float sc = e[r] / ex;
                if (sc > best || (sc == best && id < bidx)) { best = sc; bidx = id; brr = r; }
            }
        }
#pragma unroll
        for (int off = 16; off; off >>= 1) {
            float ob = __shfl_down_sync(0xFFFFFFFFu, best, off);
            int   oi = __shfl_down_sync(0xFFFFFFFFu, bidx, off);
            int   orr = __shfl_down_sync(0xFFFFFFFFu, brr, off);
            if (ob > best || (ob == best && oi < bidx)) { best = ob; bidx = oi; brr = orr; }
        }
        if (lane == 0) { wf[warp] = best; wi[warp] = bidx; wr[warp] = brr; }
        __syncthreads();
        if (warp == 0) {
            best = wf[lane]; bidx = wi[lane]; brr = wr[lane];
#pragma unroll
            for (int off = 16; off; off >>= 1) {
                float ob = __shfl_down_sync(0xFFFFFFFFu, best, off);
                int   oi = __shfl_down_sync(0xFFFFFFFFu, bidx, off);
                int   orr = __shfl_down_sync(0xFFFFFFFFu, brr, off);
                if (ob > best || (ob == best && oi < bidx)) { best = ob; bidx = oi; brr = orr; }
            }
            if (lane == 0) { s_sampled = bidx; s_rstar = brr; }
        }
        __syncthreads();
        sampled = s_sampled;
        rstar = s_rstar;
    } else {
        sampled = DIDX(0);
        rstar = 0;
    }

    const float vstar = DVAL(rstar);
    const float tlp = vstar - lZ;
    for (int r = t; r < n; r += NTHREADS) {
        if ((DVAL(r) - lZ) >= tlp) atomicAdd(&s_rank, 1);
    }
    __syncthreads();

    if (t == 0) {
        out[row] = (float)sampled;
        out[(size_t)B + (size_t)row * C] = (float)sampled;
        out[(size_t)B + (size_t)B * C + (size_t)row * C] = tlp;
        out[(size_t)B + 2 * (size_t)B * C + row] = (float)s_rank;
    }
    if (t >= 1 && t < C) {
        int r = t - 1;
        unsigned long long kv = DKEY(r);
        out[(size_t)B + (size_t)row * C + t] = (float)(~(unsigned)kv);
        out[(size_t)B + (size_t)B * C + (size_t)row * C + t] = inv_mono((unsigned)(kv >> 32)) - lZ;
    }
#undef DKEY
#undef DVAL
#undef DIDX
}

// ======================================================================
extern "C" void kernel_launch(void* const* d_in, const int* in_sizes, int n_in,
                              void* d_out, int out_size) {
    const float* logits      = (const float*)d_in[0];
    const float* temperature = (const float*)d_in[1];
    const float* min_p       = (const float*)d_in[2];
    const int*   top_k       = (const int*)d_in[3];
    const float* top_p       = (const float*)d_in[4];
    const float* q           = (const float*)d_in[5];

    int B = in_sizes[1];
    int V = in_sizes[0] / B;
    int C = (out_size / B - 2) / 2;   // num_logprobs + 1

    sampler_fused<<<B, NTHREADS>>>(logits, temperature, min_p, top_k, top_p, q,
                                   (float*)d_out, B, V, C);
}

// round 8
// speedup vs baseline: 1.5317x; 1.5217x over previous
#include <cuda_runtime.h>
#include <stdint.h>

#define NTHREADS 1024
#define NWARPS (NTHREADS / 32)
#define HBITS 13
#define NBINS (1 << HBITS)
#define BPT (NBINS / NTHREADS)      // bins per thread = 8
#define CAP 2048                    // candidate buffer per row
#define SAMP 16384                  // sample size for threshold estimation
#define TARGET 1500                 // desired E[candidate count]
#define SAMPLING_EPS 1e-5f

// order-preserving float -> uint32 map (and inverse)
__device__ __forceinline__ unsigned mono(float f) {
    unsigned u = __float_as_uint(f);
    return u ^ ((unsigned)(((int)u) >> 31) | 0x80000000u);
}
__device__ __forceinline__ float inv_mono(unsigned m) {
    unsigned u = (m & 0x80000000u) ? (m ^ 0x80000000u) : ~m;
    return __uint_as_float(u);
}

// one bitonic round's register-resident phases (j = jstart..1, jstart<=32).
__device__ __forceinline__ void reg_round(unsigned long long& a, unsigned long long& b,
                                          int i0, int i1, int lane, int kk, int jstart) {
    const bool upa = ((i0 & kk) == 0);
    const bool upb = ((i1 & kk) == 0);
#pragma unroll
    for (int j = 32; j >= 1; j >>= 1) {
        if (j > jstart) continue;
        if (j == 32) {
            unsigned long long lo = a < b ? a : b;
            unsigned long long hi = a < b ? b : a;
            a = upa ? lo : hi;
            b = upa ? hi : lo;
        } else {
            const bool lower = ((lane & j) == 0);
            unsigned long long pa = __shfl_xor_sync(0xFFFFFFFFu, a, j);
            unsigned long long pb = __shfl_xor_sync(0xFFFFFFFFu, b, j);
            bool keepMinA = (lower == upa);
            bool keepMinB = (lower == upb);
            a = keepMinA ? (a < pa ? a : pa) : (a > pa ? a : pa);
            b = keepMinB ? (b < pb ? b : pb) : (b > pb ? b : pb);
        }
    }
}

// block-wide: suffix-scan 13-bit histogram; find largest bin with suffix >= need.
// Returns bin; *s_above gets the suffix count strictly above that bin.
__device__ int find_bin(unsigned* hist, unsigned need, unsigned* wu,
                        unsigned* s_bin, unsigned* s_above) {
    const int t = threadIdx.x, lane = t & 31, warp = t >> 5;
    if (t == 0) { *s_bin = 0u; *s_above = 0u; }
    __syncthreads();                 // hist atomics complete + init
    unsigned cnt[BPT];
    unsigned csum = 0;
#pragma unroll
    for (int b = 0; b < BPT; b++) { cnt[b] = hist[t * BPT + b]; csum += cnt[b]; }
    unsigned iv = csum;
#pragma unroll
    for (int off = 1; off < 32; off <<= 1) {
        unsigned nb = __shfl_up_sync(0xFFFFFFFFu, iv, off);
        if (lane >= off) iv += nb;
    }
    if (lane == 31) wu[warp] = iv;
    __syncthreads();
    if (warp == 0) {
        unsigned wv = wu[lane];
#pragma unroll
        for (int off = 1; off < 32; off <<= 1) {
            unsigned nb = __shfl_up_sync(0xFFFFFFFFu, wv, off);
            if (lane >= off) wv += nb;
        }
        wu[lane] = wv;
    }
    __syncthreads();
    unsigned incl = iv + (warp ? wu[warp - 1] : 0u);
    unsigned Total = wu[NWARPS - 1];
    unsigned above = Total - incl;
    unsigned acc = above, prev = above;
#pragma unroll
    for (int b = BPT - 1; b >= 0; b--) {
        acc += cnt[b];               // = suffix(bin t*BPT+b)
        if (acc >= need && prev < need) { *s_bin = (unsigned)(t * BPT + b); *s_above = prev; }
        prev = acc;
    }
    __syncthreads();
    return (int)*s_bin;
}

// ======================================================================
// Fused sampler, ONE full-row read:
//   two-level sampled histogram (16K elems, 26-bit threshold) -> thr
//   single full pass: sum-exp + candidate collection (float compare only)
//   exact-histogram fallback (statistically never taken)
//   hybrid bitonic sort, min-p/top-k/top-p, race sampling, top-20, rank
// ======================================================================
__global__ __launch_bounds__(NTHREADS, 1) void sampler_fused(
    const float* __restrict__ logits,
    const float* __restrict__ temperature,
    const float* __restrict__ min_p,
    const int*   __restrict__ top_k,
    const float* __restrict__ top_p,
    const float* __restrict__ q,
    float* __restrict__ out,
    int B, int V, int C)
{
    const int row = blockIdx.x;
    const int t = threadIdx.x;
    const int lane = t & 31, warp = t >> 5;

    // 32KB buffer: hist[8192 u32]  OR  key[2048 u64] | e[2048 f32] | hd[2048 f32]
    __shared__ __align__(16) unsigned char sbuf[NBINS * 4];
    __shared__ float wf[NWARPS];
    __shared__ unsigned wu[NWARPS];
    __shared__ int wi[NWARPS], wr[NWARPS];
    __shared__ unsigned s_bin, s_above;
    __shared__ int s_cnt, s_m, s_S, s_rank, s_sampled, s_rstar;
    __shared__ float s_lz;

    unsigned* hist = (unsigned*)sbuf;
    unsigned long long* key = (unsigned long long*)sbuf;
    float* e  = (float*)(sbuf + CAP * 8);
    float* hd = (float*)(sbuf + CAP * 8 + CAP * 4);

    if (t == 0) { s_cnt = 0; s_m = 0; s_S = 0; s_rank = 0; }
#pragma unroll
    for (int z = t; z < NBINS; z += NTHREADS) hist[z] = 0u;
    __syncthreads();

    const float* __restrict__ x = logits + (size_t)row * V;
    const int V4 = V >> 2;
    const float4* __restrict__ x4 = (const float4*)x;

    // ------------- level 1: coarse 13-bit histogram of 16K sample -------------
    const int SQ = min(SAMP, V & ~3) >> 2;
    for (int i = t; i < SQ; i += NTHREADS) {
        float4 v = x4[i];
        atomicAdd(&hist[mono(v.x) >> (32 - HBITS)], 1u);
        atomicAdd(&hist[mono(v.y) >> (32 - HBITS)], 1u);
        atomicAdd(&hist[mono(v.z) >> (32 - HBITS)], 1u);
        atomicAdd(&hist[mono(v.w) >> (32 - HBITS)], 1u);
    }
    const unsigned need_samp = (unsigned)max(1ll,
        ((long long)TARGET * (long long)(SQ * 4)) / (long long)V);
    const int b1 = find_bin(hist, need_samp, wu, &s_bin, &s_above);   // syncs inside
    const unsigned need2 = need_samp - s_above;   // within-bin sample target

    // ------------- level 2: fine 13-bit histogram within coarse bin -----------
#pragma unroll
    for (int z = t; z < NBINS; z += NTHREADS) hist[z] = 0u;
    __syncthreads();
    for (int i = t; i < SQ; i += NTHREADS) {
        float4 v = x4[i];   // L1/L2 hot re-read
        unsigned u;
        u = mono(v.x); if ((int)(u >> 19) == b1) atomicAdd(&hist[(u >> 6) & 0x1FFFu], 1u);
        u = mono(v.y); if ((int)(u >> 19) == b1) atomicAdd(&hist[(u >> 6) & 0x1FFFu], 1u);
        u = mono(v.z); if ((int)(u >> 19) == b1) atomicAdd(&hist[(u >> 6) & 0x1FFFu], 1u);
        u = mono(v.w); if ((int)(u >> 19) == b1) atomicAdd(&hist[(u >> 6) & 0x1FFFu], 1u);
    }
    const int fb = find_bin(hist, need2, wu, &s_bin, &s_above);       // syncs inside
    unsigned thr = ((unsigned)b1 << 19) | ((unsigned)fb << 6);
    const float thr_f = inv_mono(thr);

    // ------------- single full pass: sum-exp + collect (float compare) --------
    float s0 = 0.f, s1 = 0.f, s2 = 0.f, s3 = 0.f;
    auto procF = [&](float4 v, int base) {
        s0 += __expf(v.x); s1 += __expf(v.y);
        s2 += __expf(v.z); s3 += __expf(v.w);
        if (v.x >= thr_f) { int p = atomicAdd(&s_cnt, 1); if (p < CAP) key[p] = ((unsigned long long)mono(v.x) << 32) | (unsigned)~(unsigned)(base + 0); }
        if (v.y >= thr_f) { int p = atomicAdd(&s_cnt, 1); if (p < CAP) key[p] = ((unsigned long long)mono(v.y) << 32) | (unsigned)~(unsigned)(base + 1); }
        if (v.z >= thr_f) { int p = atomicAdd(&s_cnt, 1); if (p < CAP) key[p] = ((unsigned long long)mono(v.z) << 32) | (unsigned)~(unsigned)(base + 2); }
        if (v.w >= thr_f) { int p = atomicAdd(&s_cnt, 1); if (p < CAP) key[p] = ((unsigned long long)mono(v.w) << 32) | (unsigned)~(unsigned)(base + 3); }
    };
    int i = t;
    for (; i + 3 * NTHREADS < V4; i += 4 * NTHREADS) {
        float4 a = x4[i];
        float4 b = x4[i + NTHREADS];
        float4 c = x4[i + 2 * NTHREADS];
        float4 d = x4[i + 3 * NTHREADS];
        procF(a, 4 * i);
        procF(b, 4 * (i + NTHREADS));
        procF(c, 4 * (i + 2 * NTHREADS));
        procF(d, 4 * (i + 3 * NTHREADS));
    }
    for (; i < V4; i += NTHREADS) procF(x4[i], 4 * i);
    for (int j = (V4 << 2) + t; j < V; j += NTHREADS) {
        float v = x[j];
        s0 += __expf(v);
        if (v >= thr_f) { int p = atomicAdd(&s_cnt, 1); if (p < CAP) key[p] = ((unsigned long long)mono(v) << 32) | (unsigned)~(unsigned)j; }
    }
    float s = (s0 + s1) + (s2 + s3);
#pragma unroll
    for (int off = 16; off; off >>= 1)
        s += __shfl_xor_sync(0xFFFFFFFFu, s, off);
    if (lane == 0) wf[warp] = s;
    __syncthreads();                 // key writes + s_cnt final + wf visible
    if (t == 0) {
        float stot = 0.f;
#pragma unroll
        for (int w2 = 0; w2 < NWARPS; w2++) stot += wf[w2];
        s_lz = logf(stot);
    }
    __syncthreads();

    // ------------- check + exact fallback (statistically never taken) ---------
    int kclip = top_k[row];
    kclip = max(1, min(kclip, V));
    const int needed = min(max(kclip, 21), CAP);
    if (s_cnt < needed || s_cnt > CAP) {
        // exact coarse histogram (clobbers keys), then recollect
#pragma unroll
        for (int z = t; z < NBINS; z += NTHREADS) hist[z] = 0u;
        __syncthreads();
        for (int ii = t; ii < V4; ii += NTHREADS) {
            float4 v = x4[ii];
            atomicAdd(&hist[mono(v.x) >> (32 - HBITS)], 1u);
            atomicAdd(&hist[mono(v.y) >> (32 - HBITS)], 1u);
            atomicAdd(&hist[mono(v.z) >> (32 - HBITS)], 1u);
            atomicAdd(&hist[mono(v.w) >> (32 - HBITS)], 1u);
        }
        for (int j = (V4 << 2) + t; j < V; j += NTHREADS)
            atomicAdd(&hist[mono(x[j]) >> (32 - HBITS)], 1u);
        int b2 = find_bin(hist, (unsigned)needed, wu, &s_bin, &s_above);
        thr = (unsigned)b2 << 19;
        if (t == 0) s_cnt = 0;
        __syncthreads();
        for (int ii = t; ii < V4; ii += NTHREADS) {
            float4 v = x4[ii];
            unsigned u;
            u = mono(v.x); if (u >= thr) { int p = atomicAdd(&s_cnt, 1); if (p < CAP) key[p] = ((unsigned long long)u << 32) | (unsigned)~(unsigned)(4 * ii + 0); }
            u = mono(v.y); if (u >= thr) { int p = atomicAdd(&s_cnt, 1); if (p < CAP) key[p] = ((unsigned long long)u << 32) | (unsigned)~(unsigned)(4 * ii + 1); }
            u = mono(v.z); if (u >= thr) { int p = atomicAdd(&s_cnt, 1); if (p < CAP) key[p] = ((unsigned long long)u << 32) | (unsigned)~(unsigned)(4 * ii + 2); }
            u = mono(v.w); if (u >= thr) { int p = atomicAdd(&s_cnt, 1); if (p < CAP) key[p] = ((unsigned long long)u << 32) | (unsigned)~(unsigned)(4 * ii + 3); }
        }
        for (int j = (V4 << 2) + t; j < V; j += NTHREADS) {
            unsigned u = mono(x[j]);
            if (u >= thr) { int p = atomicAdd(&s_cnt, 1); if (p < CAP) key[p] = ((unsigned long long)u << 32) | (unsigned)~(unsigned)j; }
        }
        __syncthreads();
    }
    const int n = min(s_cnt, CAP);
    for (int z = n + t; z < CAP; z += NTHREADS) key[z] = 0ULL;  // sentinel
    __syncthreads();
    const float lZ = s_lz;

    // ---------------- hybrid bitonic sort (ascending) -------------------------
    const int i0 = 64 * warp + lane;
    const int i1 = i0 + 32;
    {
        unsigned long long a = key[i0], b = key[i1];
#pragma unroll
        for (int kk = 2; kk <= 64; kk <<= 1)
            reg_round(a, b, i0, i1, lane, kk, (kk >> 1) > 32 ? 32 : (kk >> 1));
        key[i0] = a; key[i1] = b;
        __syncthreads();
        for (int kk = 128; kk <= CAP; kk <<= 1) {
            for (int j = kk >> 1; j >= 64; j >>= 1) {
#pragma unroll
                for (int w2 = 0; w2 < CAP / NTHREADS; w2++) {
                    int idx = t + w2 * NTHREADS;
                    int l2 = idx ^ j;
                    if (l2 > idx) {
                        unsigned long long av = key[idx], bv = key[l2];
                        bool sw = ((idx & kk) == 0) ? (av > bv) : (av < bv);
                        if (sw) { key[idx] = bv; key[l2] = av; }
                    }
                }
                __syncthreads();
            }
            a = key[i0]; b = key[i1];
            reg_round(a, b, i0, i1, lane, kk, 32);
            key[i0] = a; key[i1] = b;
            __syncthreads();
        }
    }

#define DKEY(r) (key[CAP - 1 - (r)])
#define DVAL(r) inv_mono((unsigned)(DKEY(r) >> 32))
#define DIDX(r) ((int)(~(unsigned)DKEY(r)))

    // ---------------- per-row scalars (rmax = top candidate) ------------------
    const float rmax = DVAL(0);
    const float temp = temperature[row];
    const float mp   = min_p[row];
    const float tp   = top_p[row];
    const int kk_ = kclip;
    const float t_mp = rmax + temp * logf(mp);

    for (int r = t; r < n; r += NTHREADS)
        if (DVAL(r) >= t_mp) atomicAdd(&s_m, 1);
    __syncthreads();
    const int mcnt = s_m;

    if (mcnt >= kk_) {
        float kth = DVAL(kk_ - 1);
        for (int r = t; r < n; r += NTHREADS)
            if (DVAL(r) >= kth) atomicAdd(&s_S, 1);
    }
    __syncthreads();
    const int S = (mcnt >= kk_) ? min(s_S, CAP) : mcnt;

    const bool greedy = (temp < SAMPLING_EPS);
    int sampled, rstar;

    if (!greedy) {
        const float lt0 = DVAL(0) / temp;
        for (int r = t; r < CAP; r += NTHREADS) {
            float ev = 0.f;
            if (r < S) ev = expf(DVAL(r) / temp - lt0);
            e[r] = ev;
        }
        __syncthreads();

        float a0 = e[2 * t], a1 = e[2 * t + 1];
        float tsum = a0 + a1;
        float sv = tsum;
#pragma unroll
        for (int off = 1; off < 32; off <<= 1) {
            float nb = __shfl_up_sync(0xFFFFFFFFu, sv, off);
            if (lane >= off) sv += nb;
        }
        if (lane == 31) wf[warp] = sv;
        __syncthreads();
        if (warp == 0) {
            float wv = wf[lane];
#pragma unroll
            for (int off = 1; off < 32; off <<= 1) {
                float nb = __shfl_up_sync(0xFFFFFFFFu, wv, off);
                if (lane >= off) wv += nb;
            }
            wf[lane] = wv;
        }
        __syncthreads();
        float inclf = sv + (warp ? wf[warp - 1] : 0.f);
        const float Z = wf[NWARPS - 1];
        float excl = inclf - tsum;
        hd[2 * t]     = excl;
        hd[2 * t + 1] = excl + a0;
        __syncthreads();

        const float c1 = (1.f - tp) * Z;
        const float* __restrict__ qrow = q + (size_t)row * V;
        float best = -1.f;
        int bidx = 0x7FFFFFFF, brr = 0;
        for (int r = t; r < S; r += NTHREADS) {
            if (r == 0 || (Z - hd[r]) > c1) {
                int id = DIDX(r);
                float qv = qrow[id];
                float ex = -logf(fmaxf(qv, 1e-10f));
                float sc = e[r] / ex;
                if (sc > best || (sc == best && id < bidx)) { best = sc; bidx = id; brr = r; }
            }
        }
#pragma unroll
        for (int off = 16; off; off >>= 1) {
            float ob = __shfl_down_sync(0xFFFFFFFFu, best, off);
            int   oi = __shfl_down_sync(0xFFFFFFFFu, bidx, off);
            int   orr = __shfl_down_sync(0xFFFFFFFFu, brr, off);
            if (ob > best || (ob == best && oi < bidx)) { best = ob; bidx = oi; brr = orr; }
        }
        if (lane == 0) { wf[warp] = best; wi[warp] = bidx; wr[warp] = brr; }
        __syncthreads();
        if (warp == 0) {
            best = wf[lane]; bidx = wi[lane]; brr = wr[lane];
#pragma unroll
            for (int off = 16; off; off >>= 1) {
                float ob = __shfl_down_sync(0xFFFFFFFFu, best, off);
                int   oi = __shfl_down_sync(0xFFFFFFFFu, bidx, off);
                int   orr = __shfl_down_sync(0xFFFFFFFFu, brr, off);
                if (ob > best || (ob == best && oi < bidx)) { best = ob; bidx = oi; brr = orr; }
            }
            if (lane == 0) { s_sampled = bidx; s_rstar = brr; }
        }
        __syncthreads();
        sampled = s_sampled;
        rstar = s_rstar;
    } else {
        sampled = DIDX(0);
        rstar = 0;
    }

    const float vstar = DVAL(rstar);
    const float tlp = vstar - lZ;
    for (int r = t; r < n; r += NTHREADS) {
        if ((DVAL(r) - lZ) >= tlp) atomicAdd(&s_rank, 1);
    }
    __syncthreads();

    if (t == 0) {
        out[row] = (float)sampled;
        out[(size_t)B + (size_t)row * C] = (float)sampled;
        out[(size_t)B + (size_t)B * C + (size_t)row * C] = tlp;
        out[(size_t)B + 2 * (size_t)B * C + row] = (float)s_rank;
    }
    if (t >= 1 && t < C) {
        int r = t - 1;
        unsigned long long kv = DKEY(r);
        out[(size_t)B + (size_t)row * C + t] = (float)(~(unsigned)kv);
        out[(size_t)B + (size_t)B * C + (size_t)row * C + t] = inv_mono((unsigned)(kv >> 32)) - lZ;
    }
#undef DKEY
#undef DVAL
#undef DIDX
}

// ======================================================================
extern "C" void kernel_launch(void* const* d_in, const int* in_sizes, int n_in,
                              void* d_out, int out_size) {
    const float* logits      = (const float*)d_in[0];
    const float* temperature = (const float*)d_in[1];
    const float* min_p       = (const float*)d_in[2];
    const int*   top_k       = (const int*)d_in[3];
    const float* top_p       = (const float*)d_in[4];
    const float* q           = (const float*)d_in[5];

    int B = in_sizes[1];
    int V = in_sizes[0] / B;
    int C = (out_size / B - 2) / 2;   // num_logprobs + 1

    sampler_fused<<<B, NTHREADS>>>(logits, temperature, min_p, top_k, top_p, q,
                                   (float*)d_out, B, V, C);
}